// round 11
// baseline (speedup 1.0000x reference)
#include <cuda_runtime.h>
#include <cuda_bf16.h>
#include <math.h>
#include <cstdint>

// ---------------- problem constants ----------------
#define BB       256
#define DMODEL   2048
#define DINNER   8192
#define DSTATE   16
#define DTRANK   128
#define XPN      (DTRANK + 2*DSTATE)   // 160

// ---------------- scratch (device globals; no allocation) ----------------
__device__ float g_xz [BB * 2 * DINNER];   // xi | z
__device__ float g_xc [BB * DINNER];
__device__ float g_xdb[BB * XPN];
__device__ float g_dt [BB * DINNER];
__device__ float g_A  [DINNER * DSTATE];

// bf16 hi/lo split tensors (A-operands only; tiny)
__device__ __nv_bfloat16 g_xhi  [BB * DMODEL];
__device__ __nv_bfloat16 g_xlo  [BB * DMODEL];
__device__ __nv_bfloat16 g_yhi  [BB * DINNER];
__device__ __nv_bfloat16 g_ylo  [BB * DINNER];

// ---------------- helpers ----------------
__device__ __forceinline__ uint32_t smem_u32(const void* p) {
    uint32_t a;
    asm("{ .reg .u64 t; cvta.to.shared.u64 t, %1; cvt.u32.u64 %0, t; }" : "=r"(a) : "l"(p));
    return a;
}

__device__ __forceinline__ void ldmx4(uint32_t* r, uint32_t addr) {
    asm volatile("ldmatrix.sync.aligned.m8n8.x4.shared.b16 {%0,%1,%2,%3}, [%4];"
        : "=r"(r[0]), "=r"(r[1]), "=r"(r[2]), "=r"(r[3]) : "r"(addr));
}

__device__ __forceinline__ void mma16816(float* d, const uint32_t* a,
                                         uint32_t b0, uint32_t b1) {
    asm volatile(
        "mma.sync.aligned.m16n8k16.row.col.f32.bf16.bf16.f32 "
        "{%0,%1,%2,%3}, {%4,%5,%6,%7}, {%8,%9}, {%0,%1,%2,%3};"
        : "+f"(d[0]), "+f"(d[1]), "+f"(d[2]), "+f"(d[3])
        : "r"(a[0]), "r"(a[1]), "r"(a[2]), "r"(a[3]), "r"(b0), "r"(b1));
}

__device__ __forceinline__ void cp16(uint32_t s, const void* g) {
    asm volatile("cp.async.cg.shared.global [%0], [%1], 16;" :: "r"(s), "l"(g));
}
#define CP_COMMIT() asm volatile("cp.async.commit_group;" ::: "memory")
#define CP_WAIT(n)  asm volatile("cp.async.wait_group %0;" :: "n"(n) : "memory")

#define STS128(addr, r) \
    asm volatile("st.shared.v4.b32 [%0], {%1,%2,%3,%4};" \
        :: "r"(addr), "r"((r)[0]), "r"((r)[1]), "r"((r)[2]), "r"((r)[3]) : "memory")

// fp32 pair -> bf16x2 hi (truncation via PRMT) + bf16x2 lo (residual, RN)
__device__ __forceinline__ void cvt_pair(float2 v, uint32_t& hi, uint32_t& lo) {
    uint32_t ax = __float_as_uint(v.x), ay = __float_as_uint(v.y);
    uint32_t h;
    asm("prmt.b32 %0, %1, %2, 0x7632;" : "=r"(h) : "r"(ax), "r"(ay));
    float hx = __uint_as_float(ax & 0xFFFF0000u);
    float hy = __uint_as_float(ay & 0xFFFF0000u);
    __nv_bfloat162 l = __floats2bfloat162_rn(v.x - hx, v.y - hy);
    hi = h;
    lo = *(uint32_t*)&l;
}

// ---------------- HMMA bf16 hi/lo GEMM ----------------
// C[M,N] (+)= (Ah+Al)[M,K] * Bf[N,K]^T; Bf fp32 converted to bf16 hi/lo by the
// LOADER (once per element), compute loop is pure ldmatrix+MMA.
// 3-product compensation (AhBh + AlBh + AhBl).
// 256 threads, tile 128x128x32. A: cp.async 3 stages x 16 KB. B: LDG->reg->
// cvt->STS, 2 stages x 16 KB. Total 80 KB -> 2 CTAs/SM. One sync per iter.
// Swizzle (both operands): 64 B rows, chunk c ^ ((row>>1)&3).
// EPI: 0 = store, 1 = atomicAdd (split-K). iters must be >= 3.
#define GBM 128
#define GBN 128
#define GBK 32
#define A_STG 16384
#define B_BASE 49152
#define B_STG 16384
#define HSM_TOT 81920

template<int EPI, int SPLITK>
__global__ void __launch_bounds__(256, 2)
hmma_gemm(const __nv_bfloat16* __restrict__ Ah, const __nv_bfloat16* __restrict__ Al,
          const float* __restrict__ Bf,
          float* __restrict__ C, int ldc, int K)
{
    extern __shared__ char smraw[];

    const int tid = threadIdx.x;
    const int n0  = blockIdx.x * GBN;
    const int m0  = blockIdx.y * GBM;
    const int kChunk = K / SPLITK;
    const int kb  = blockIdx.z * kChunk;
    const int iters = kChunk / GBK;

    const uint32_t usm = smem_u32(smraw);

    // ---- A loader (cp.async): 512 chunks hi + 512 lo, 2 each per thread ----
    auto issueA = [&](uint32_t sbase, int koff) {
        #pragma unroll
        for (int u = 0; u < 2; u++) {
            int idx = u * 256 + tid;
            int r   = idx >> 2;
            int c   = idx & 3;
            size_t ga   = (size_t)(m0 + r) * K + koff + c * 8;
            uint32_t so = (uint32_t)(r * 64 + ((c ^ ((r >> 1) & 3)) * 16));
            cp16(sbase + so, Ah + ga);
            cp16(sbase + 8192 + so, Al + ga);
        }
    };

    // ---- B loader: half row (16 fp32) per thread ----
    const int br  = tid >> 1;              // B row (n)
    const int bkh = (tid & 1) * 16;        // k offset (floats)
    float4 rb[4];
    auto ldgB = [&](int koff) {
        const float* p = Bf + (size_t)(n0 + br) * K + koff + bkh;
        rb[0] = *(const float4*)p;
        rb[1] = *(const float4*)(p + 4);
        rb[2] = *(const float4*)(p + 8);
        rb[3] = *(const float4*)(p + 12);
    };
    auto stsB = [&](uint32_t sbase) {       // sbase = BH base of stage
        const int c0 = (tid & 1) * 2;       // first 16B chunk index
        uint32_t h[4], l[4];
        cvt_pair(make_float2(rb[0].x, rb[0].y), h[0], l[0]);
        cvt_pair(make_float2(rb[0].z, rb[0].w), h[1], l[1]);
        cvt_pair(make_float2(rb[1].x, rb[1].y), h[2], l[2]);
        cvt_pair(make_float2(rb[1].z, rb[1].w), h[3], l[3]);
        uint32_t o0 = (uint32_t)(br * 64 + ((c0 ^ ((br >> 1) & 3)) * 16));
        STS128(sbase + o0, h);
        STS128(sbase + 8192 + o0, l);
        cvt_pair(make_float2(rb[2].x, rb[2].y), h[0], l[0]);
        cvt_pair(make_float2(rb[2].z, rb[2].w), h[1], l[1]);
        cvt_pair(make_float2(rb[3].x, rb[3].y), h[2], l[2]);
        cvt_pair(make_float2(rb[3].z, rb[3].w), h[3], l[3]);
        uint32_t o1 = (uint32_t)(br * 64 + (((c0 + 1) ^ ((br >> 1) & 3)) * 16));
        STS128(sbase + o1, h);
        STS128(sbase + 8192 + o1, l);
    };

    // prologue
    issueA(usm, kb);           CP_COMMIT();
    issueA(usm + A_STG, kb + GBK); CP_COMMIT();
    ldgB(kb);

    // compute mapping: 2m x 4n warps, warp tile 64x32
    const int w    = tid >> 5;
    const int lane = tid & 31;
    const int wm   = (w & 1) * 64;
    const int wn   = (w >> 1) * 32;
    const int g    = lane >> 3;
    const int rr   = lane & 7;

    float acc[4][4][4];
    #pragma unroll
    for (int i = 0; i < 4; i++)
        #pragma unroll
        for (int j = 0; j < 4; j++)
            #pragma unroll
            for (int c = 0; c < 4; c++) acc[i][j][c] = 0.0f;

    int sA = 0, sB = 0;
    for (int it = 0; it < iters; ++it) {
        CP_WAIT(1);                          // A stage sA complete
        stsB(usm + B_BASE + (uint32_t)sB * B_STG);   // B(it) into stage sB
        __syncthreads();                     // A+B visible; it-1 compute drained

        if (it + 2 < iters)
            issueA(usm + (uint32_t)((it + 2) % 3) * A_STG, kb + (it + 2) * GBK);
        CP_COMMIT();                         // uniform group counting
        if (it + 1 < iters) ldgB(kb + (it + 1) * GBK);

        const uint32_t uAh = usm + (uint32_t)sA * A_STG;
        const uint32_t uAl = uAh + 8192;
        const uint32_t uBh = usm + B_BASE + (uint32_t)sB * B_STG;
        const uint32_t uBl = uBh + 8192;

        #pragma unroll
        for (int ks = 0; ks < 2; ks++) {
            const int cc = ks * 2 + (g >> 1);   // 16B chunk within row

            uint32_t bh[4][2], bl[4][2];
            #pragma unroll
            for (int pi = 0; pi < 2; pi++) {
                int brow = wn + pi * 16 + (g & 1) * 8 + rr;
                uint32_t off = (uint32_t)(brow * 64 + ((cc ^ ((brow >> 1) & 3)) * 16));
                uint32_t t[4];
                ldmx4(t, uBh + off);
                bh[pi*2+0][0] = t[0]; bh[pi*2+0][1] = t[2];
                bh[pi*2+1][0] = t[1]; bh[pi*2+1][1] = t[3];
                ldmx4(t, uBl + off);
                bl[pi*2+0][0] = t[0]; bl[pi*2+0][1] = t[2];
                bl[pi*2+1][0] = t[1]; bl[pi*2+1][1] = t[3];
            }
            #pragma unroll
            for (int mi = 0; mi < 4; mi++) {
                int arow = wm + mi * 16 + (g & 1) * 8 + rr;
                uint32_t off = (uint32_t)(arow * 64 + ((cc ^ ((arow >> 1) & 3)) * 16));
                uint32_t ah[4], al[4];
                ldmx4(ah, uAh + off);
                ldmx4(al, uAl + off);
                #pragma unroll
                for (int ni = 0; ni < 4; ni++) {
                    mma16816(acc[mi][ni], ah, bh[ni][0], bh[ni][1]);
                    mma16816(acc[mi][ni], al, bh[ni][0], bh[ni][1]);
                    mma16816(acc[mi][ni], ah, bl[ni][0], bl[ni][1]);
                }
            }
        }
        sA = (sA == 2) ? 0 : sA + 1;
        sB ^= 1;
    }

    // ---- epilogue ----
    const int erow = lane >> 2;
    const int ecol = (lane & 3) * 2;
    #pragma unroll
    for (int mi = 0; mi < 4; mi++) {
        #pragma unroll
        for (int ni = 0; ni < 4; ni++) {
            int r0 = m0 + wm + mi * 16 + erow;
            int c0 = n0 + wn + ni * 8 + ecol;
            float* p0 = C + (size_t)r0 * ldc + c0;
            float* p1 = C + (size_t)(r0 + 8) * ldc + c0;
            if (EPI == 0) {
                *(float2*)p0 = make_float2(acc[mi][ni][0], acc[mi][ni][1]);
                *(float2*)p1 = make_float2(acc[mi][ni][2], acc[mi][ni][3]);
            } else {
                atomicAdd(p0,     acc[mi][ni][0]);
                atomicAdd(p0 + 1, acc[mi][ni][1]);
                atomicAdd(p1,     acc[mi][ni][2]);
                atomicAdd(p1 + 1, acc[mi][ni][3]);
            }
        }
    }
}

// ---------------- small helpers ----------------
__global__ void zero_kernel(float* __restrict__ p, int n) {
    int i = blockIdx.x * blockDim.x + threadIdx.x;
    if (i < n) p[i] = 0.0f;
}

__global__ void precompute_A_kernel(const float* __restrict__ A_log) {
    int i = blockIdx.x * blockDim.x + threadIdx.x;
    if (i < DINNER * DSTATE) g_A[i] = -expf(A_log[i]);
}

// split fp32 -> bf16 hi + bf16 lo (residual), float4-vectorized (A operands only)
__global__ void split_bf16_kernel(const float4* __restrict__ in,
                                  __nv_bfloat162* __restrict__ hi,
                                  __nv_bfloat162* __restrict__ lo, int n4) {
    int i = blockIdx.x * blockDim.x + threadIdx.x;
    if (i >= n4) return;
    float4 v = in[i];
    __nv_bfloat162 h01 = __floats2bfloat162_rn(v.x, v.y);
    __nv_bfloat162 h23 = __floats2bfloat162_rn(v.z, v.w);
    float lx = v.x - __bfloat162float(h01.x);
    float ly = v.y - __bfloat162float(h01.y);
    float lz = v.z - __bfloat162float(h23.x);
    float lw = v.w - __bfloat162float(h23.y);
    hi[2*i]   = h01;
    hi[2*i+1] = h23;
    lo[2*i]   = __floats2bfloat162_rn(lx, ly);
    lo[2*i+1] = __floats2bfloat162_rn(lz, lw);
}

// ---------------- fp32 tiled SGEMM (small GEMMs) ----------------
template<int BM, int BN, int BK, int TM, int TN, int EPI>
__global__ void __launch_bounds__((BM/TM)*(BN/TN))
sgemm_nt(const float* __restrict__ A, int lda,
         const float* __restrict__ Bm, int ldb,
         float* __restrict__ C, int ldc,
         int M, int N, int K, int kChunk,
         const float* __restrict__ bias)
{
    constexpr int THREADS = (BM/TM)*(BN/TN);
    constexpr int KQ = BK / 4;
    constexpr int A4 = BM * BK / 4;
    constexpr int B4 = BN * BK / 4;

    __shared__ float As[BK][BM];
    __shared__ float Bs[BK][BN];

    const int tid = threadIdx.x;
    const int n0  = blockIdx.x * BN;
    const int m0  = blockIdx.y * BM;
    const int kb  = blockIdx.z * kChunk;
    const int ke  = (kb + kChunk < K) ? (kb + kChunk) : K;

    const int tc = tid % (BN / TN);
    const int tr = tid / (BN / TN);

    float acc[TM][TN];
    #pragma unroll
    for (int i = 0; i < TM; i++)
        #pragma unroll
        for (int j = 0; j < TN; j++) acc[i][j] = 0.0f;

    for (int k0 = kb; k0 < ke; k0 += BK) {
        #pragma unroll
        for (int i = tid; i < A4; i += THREADS) {
            int m  = i / KQ;
            int kq = i % KQ;
            float4 v = *(const float4*)&A[(size_t)(m0 + m) * lda + k0 + kq * 4];
            As[kq*4+0][m] = v.x; As[kq*4+1][m] = v.y;
            As[kq*4+2][m] = v.z; As[kq*4+3][m] = v.w;
        }
        #pragma unroll
        for (int i = tid; i < B4; i += THREADS) {
            int n  = i / KQ;
            int kq = i % KQ;
            float4 v = *(const float4*)&Bm[(size_t)(n0 + n) * ldb + k0 + kq * 4];
            Bs[kq*4+0][n] = v.x; Bs[kq*4+1][n] = v.y;
            Bs[kq*4+2][n] = v.z; Bs[kq*4+3][n] = v.w;
        }
        __syncthreads();

        #pragma unroll
        for (int kk = 0; kk < BK; kk++) {
            float a[TM], b[TN];
            #pragma unroll
            for (int i = 0; i < TM; i++) a[i] = As[kk][tr*TM + i];
            #pragma unroll
            for (int j = 0; j < TN; j++) b[j] = Bs[kk][tc*TN + j];
            #pragma unroll
            for (int i = 0; i < TM; i++)
                #pragma unroll
                for (int j = 0; j < TN; j++)
                    acc[i][j] = fmaf(a[i], b[j], acc[i][j]);
        }
        __syncthreads();
    }

    #pragma unroll
    for (int i = 0; i < TM; i++) {
        int m = m0 + tr*TM + i;
        #pragma unroll
        for (int j = 0; j < TN; j++) {
            int n = n0 + tc*TN + j;
            float v = acc[i][j];
            if (EPI == 0) {
                C[(size_t)m * ldc + n] = v;
            } else if (EPI == 1) {
                atomicAdd(&C[(size_t)m * ldc + n], v);
            } else {
                float x = v + bias[n];
                float r2 = fmaxf(x, 0.0f) + log1pf(__expf(-fabsf(x)));
                C[(size_t)m * ldc + n] = r2;
            }
        }
    }
}

// ---------------- conv window shift + SiLU ----------------
__global__ void conv_kernel(const float* __restrict__ cs_in,
                            const float* __restrict__ conv_w,
                            const float* __restrict__ conv_b,
                            float* __restrict__ cs_out)
{
    int idx = blockIdx.x * blockDim.x + threadIdx.x;
    int b = idx >> 13;
    int d = idx & (DINNER - 1);
    float4 cs = ((const float4*)cs_in)[idx];
    float4 w  = ((const float4*)conv_w)[d];
    float xi  = g_xz[(size_t)b * (2*DINNER) + d];
    float s = cs.y*w.x + cs.z*w.y + cs.w*w.z + xi*w.w + conv_b[d];
    float sig = 1.0f / (1.0f + __expf(-s));
    g_xc[idx] = s * sig;
    ((float4*)cs_out)[idx] = make_float4(cs.y, cs.z, cs.w, xi);
}

// ---------------- SSM state update + y (emits y as bf16 hi/lo) --------------
__global__ void ssm_kernel(const float* __restrict__ ssm_in,
                           const float* __restrict__ D_param,
                           float* __restrict__ ssm_out)
{
    __shared__ float bm[DSTATE], cm[DSTATE];
    const int b = blockIdx.y;
    const int d = blockIdx.x * blockDim.x + threadIdx.x;
    if (threadIdx.x < 2*DSTATE) {
        float v = g_xdb[b * XPN + DTRANK + threadIdx.x];
        if (threadIdx.x < DSTATE) bm[threadIdx.x] = v;
        else                      cm[threadIdx.x - DSTATE] = v;
    }
    __syncthreads();

    const int bd = b * DINNER + d;
    const float dtv = g_dt[bd];
    const float xcv = g_xc[bd];
    const float xdt = xcv * dtv;
    const size_t base = (size_t)bd * DSTATE;

    float yacc = 0.0f;
    #pragma unroll
    for (int n = 0; n < DSTATE; n += 4) {
        float4 a  = *(const float4*)&g_A[d * DSTATE + n];
        float4 st = *(const float4*)&ssm_in[base + n];
        float4 ns;
        ns.x = st.x * __expf(a.x * dtv) + xdt * bm[n+0];
        ns.y = st.y * __expf(a.y * dtv) + xdt * bm[n+1];
        ns.z = st.z * __expf(a.z * dtv) + xdt * bm[n+2];
        ns.w = st.w * __expf(a.w * dtv) + xdt * bm[n+3];
        yacc += ns.x * cm[n+0] + ns.y * cm[n+1] + ns.z * cm[n+2] + ns.w * cm[n+3];
        *(float4*)&ssm_out[base + n] = ns;
    }
    yacc += D_param[d] * xcv;
    float zv = g_xz[(size_t)b * (2*DINNER) + DINNER + d];
    yacc *= zv / (1.0f + __expf(-zv));

    __nv_bfloat16 h = __float2bfloat16(yacc);
    g_yhi[bd] = h;
    g_ylo[bd] = __float2bfloat16(yacc - __bfloat162float(h));
}

// ---------------- launch ----------------
extern "C" void kernel_launch(void* const* d_in, const int* in_sizes, int n_in,
                              void* d_out, int out_size)
{
    const float* x       = (const float*)d_in[0];
    const float* cs_in   = (const float*)d_in[1];
    const float* ssm_in  = (const float*)d_in[2];
    const float* W_in    = (const float*)d_in[3];
    const float* conv_w  = (const float*)d_in[4];
    const float* conv_b  = (const float*)d_in[5];
    const float* W_xproj = (const float*)d_in[6];
    const float* W_dt    = (const float*)d_in[7];
    const float* b_dt    = (const float*)d_in[8];
    const float* A_log   = (const float*)d_in[9];
    const float* D_param = (const float*)d_in[10];
    const float* W_out   = (const float*)d_in[11];

    float* out     = (float*)d_out;
    float* cs_out  = out + (size_t)BB * DMODEL;
    float* ssm_out = cs_out + (size_t)BB * DINNER * 4;

    void *p_xz, *p_xc, *p_xdb, *p_dt, *p_xhi, *p_xlo, *p_yhi, *p_ylo;
    cudaGetSymbolAddress(&p_xz,  g_xz);
    cudaGetSymbolAddress(&p_xc,  g_xc);
    cudaGetSymbolAddress(&p_xdb, g_xdb);
    cudaGetSymbolAddress(&p_dt,  g_dt);
    cudaGetSymbolAddress(&p_xhi, g_xhi);
    cudaGetSymbolAddress(&p_xlo, g_xlo);
    cudaGetSymbolAddress(&p_yhi, g_yhi);
    cudaGetSymbolAddress(&p_ylo, g_ylo);

    cudaFuncSetAttribute(hmma_gemm<0,1>, cudaFuncAttributeMaxDynamicSharedMemorySize, HSM_TOT);
    cudaFuncSetAttribute(hmma_gemm<1,4>, cudaFuncAttributeMaxDynamicSharedMemorySize, HSM_TOT);

    // launches 0-2, then GEMM1 as the 4th launch (ncu window profiles index 3)
    zero_kernel<<<(BB*XPN + 255)/256, 256>>>((float*)p_xdb, BB*XPN);
    zero_kernel<<<(BB*DMODEL + 255)/256, 256>>>(out, BB*DMODEL);
    split_bf16_kernel<<<(BB*DMODEL/4 + 255)/256, 256>>>(
        (const float4*)x, (__nv_bfloat162*)p_xhi, (__nv_bfloat162*)p_xlo, BB*DMODEL/4);

    // GEMM1: xz[256,16384] = x @ W_in^T   (B = W_in fp32, loader-converted)
    hmma_gemm<0,1><<<dim3((2*DINNER)/GBN, BB/GBM, 1), 256, HSM_TOT>>>(
        (const __nv_bfloat16*)p_xhi, (const __nv_bfloat16*)p_xlo,
        W_in, (float*)p_xz, 2*DINNER, DMODEL);

    precompute_A_kernel<<<(DINNER*DSTATE + 255)/256, 256>>>(A_log);

    // conv + SiLU
    conv_kernel<<<(BB*DINNER)/256, 256>>>(cs_in, conv_w, conv_b, cs_out);

    // GEMM3: x_db[256,160] = xc @ W_xproj^T  (fp32, BK=32, split-K=16, atomic)
    sgemm_nt<64,32,32,4,4,1><<<dim3(XPN/32, BB/64, 16), 128>>>(
        (const float*)p_xc, DINNER, W_xproj, DINNER, (float*)p_xdb, XPN,
        BB, XPN, DINNER, DINNER/16, nullptr);

    // GEMM4: dt[256,8192] = softplus(x_db[:, :128] @ W_dt^T + b_dt)  (fp32, BK=32)
    sgemm_nt<64,64,32,4,4,2><<<dim3(DINNER/64, BB/64, 1), 256>>>(
        (const float*)p_xdb, XPN, W_dt, DTRANK, (float*)p_dt, DINNER,
        BB, DINNER, DTRANK, DTRANK, b_dt);

    // SSM update + y (emits yhi/ylo)
    ssm_kernel<<<dim3(DINNER/256, BB), 256>>>(ssm_in, D_param, ssm_out);

    // GEMM6: out[256,2048] = y @ W_out^T  (B = W_out fp32, split-K=4, atomic)
    hmma_gemm<1,4><<<dim3(DMODEL/GBN, BB/GBM, 4), 256, HSM_TOT>>>(
        (const __nv_bfloat16*)p_yhi, (const __nv_bfloat16*)p_ylo,
        W_out, out, DMODEL, DINNER);
}

// round 12
// speedup vs baseline: 1.1572x; 1.1572x over previous
#include <cuda_runtime.h>
#include <cuda_bf16.h>
#include <math.h>
#include <cstdint>

// ---------------- problem constants ----------------
#define BB       256
#define DMODEL   2048
#define DINNER   8192
#define DSTATE   16
#define DTRANK   128
#define XPN      (DTRANK + 2*DSTATE)   // 160

// ---------------- scratch (device globals; no allocation) ----------------
__device__ float g_xz [BB * 2 * DINNER];   // xi | z
__device__ float g_xc [BB * DINNER];
__device__ float g_xdb[BB * XPN];
__device__ float g_dt [BB * DINNER];
__device__ float g_A  [DINNER * DSTATE];

// bf16 hi/lo split tensors (A-operands only; tiny)
__device__ __nv_bfloat16 g_xhi  [BB * DMODEL];
__device__ __nv_bfloat16 g_xlo  [BB * DMODEL];
__device__ __nv_bfloat16 g_yhi  [BB * DINNER];
__device__ __nv_bfloat16 g_ylo  [BB * DINNER];

// ---------------- helpers ----------------
__device__ __forceinline__ uint32_t smem_u32(const void* p) {
    uint32_t a;
    asm("{ .reg .u64 t; cvta.to.shared.u64 t, %1; cvt.u32.u64 %0, t; }" : "=r"(a) : "l"(p));
    return a;
}

__device__ __forceinline__ void ldmx4(uint32_t* r, uint32_t addr) {
    asm volatile("ldmatrix.sync.aligned.m8n8.x4.shared.b16 {%0,%1,%2,%3}, [%4];"
        : "=r"(r[0]), "=r"(r[1]), "=r"(r[2]), "=r"(r[3]) : "r"(addr));
}

__device__ __forceinline__ void mma16816(float* d, const uint32_t* a,
                                         uint32_t b0, uint32_t b1) {
    asm volatile(
        "mma.sync.aligned.m16n8k16.row.col.f32.bf16.bf16.f32 "
        "{%0,%1,%2,%3}, {%4,%5,%6,%7}, {%8,%9}, {%0,%1,%2,%3};"
        : "+f"(d[0]), "+f"(d[1]), "+f"(d[2]), "+f"(d[3])
        : "r"(a[0]), "r"(a[1]), "r"(a[2]), "r"(a[3]), "r"(b0), "r"(b1));
}

__device__ __forceinline__ void cp16(uint32_t s, const void* g) {
    asm volatile("cp.async.cg.shared.global [%0], [%1], 16;" :: "r"(s), "l"(g));
}
#define CP_COMMIT() asm volatile("cp.async.commit_group;" ::: "memory")
#define CP_WAIT(n)  asm volatile("cp.async.wait_group %0;" :: "n"(n) : "memory")

// fp32 pair -> bf16x2 hi (truncation via PRMT) + bf16x2 lo (residual, RN)
__device__ __forceinline__ void cvt_pair(float2 v, uint32_t& hi, uint32_t& lo) {
    uint32_t ax = __float_as_uint(v.x), ay = __float_as_uint(v.y);
    uint32_t h;
    asm("prmt.b32 %0, %1, %2, 0x7632;" : "=r"(h) : "r"(ax), "r"(ay));
    float hx = __uint_as_float(ax & 0xFFFF0000u);
    float hy = __uint_as_float(ay & 0xFFFF0000u);
    __nv_bfloat162 l = __floats2bfloat162_rn(v.x - hx, v.y - hy);
    hi = h;
    lo = *(uint32_t*)&l;
}

// ---------------- HMMA bf16 hi/lo GEMM ----------------
// C[M,N] (+)= (Ah+Al)[M,K] * Bf[N,K]^T with Bf fp32 split to hi/lo in-register
// inside the compute loop (R10 design). 3-product compensation.
// 256 threads, tile 128x128x32, 3-stage cp.async (32 KB/stage, 96 KB -> 2 CTAs/SM).
// SINGLE __syncthreads per iteration: prologue fills 2 stages; each iter issues
// stage it+2 right after the barrier (the barrier proves all warps finished
// reading the stage being overwritten, consumed at it-1).
// A layout: 64 B rows, chunk swizzle c^((r>>1)&3). B: 128 B fp32 rows, c^(r&7).
// EPI: 0 = store, 1 = atomicAdd (split-K). iters must be >= 3.
#define GBM 128
#define GBN 128
#define GBK 32
#define AH_B 0
#define AL_B 8192
#define BF_B 16384
#define STG_BYTES 32768
#define NSTAGE 3

template<int EPI, int SPLITK>
__global__ void __launch_bounds__(256, 2)
hmma_gemm(const __nv_bfloat16* __restrict__ Ah, const __nv_bfloat16* __restrict__ Al,
          const float* __restrict__ Bf,
          float* __restrict__ C, int ldc, int K)
{
    extern __shared__ char smraw[];
    const float* smf = (const float*)smraw;

    const int tid = threadIdx.x;
    const int n0  = blockIdx.x * GBN;
    const int m0  = blockIdx.y * GBM;
    const int kChunk = K / SPLITK;
    const int kb  = blockIdx.z * kChunk;
    const int iters = kChunk / GBK;

    const uint32_t usm = smem_u32(smraw);

    auto issue = [&](uint32_t sbase, int koff) {
        // A hi/lo: 512 chunks each (128 rows x 4 x 8-bf16 chunks), 2 per thread
        #pragma unroll
        for (int u = 0; u < 2; u++) {
            int idx = u * 256 + tid;
            int r   = idx >> 2;
            int c   = idx & 3;
            size_t ga   = (size_t)(m0 + r) * K + koff + c * 8;
            uint32_t so = (uint32_t)(r * 64 + ((c ^ ((r >> 1) & 3)) * 16));
            cp16(sbase + AH_B + so, Ah + ga);
            cp16(sbase + AL_B + so, Al + ga);
        }
        // B fp32: 1024 chunks (128 rows x 8 x 4-float chunks), 4 per thread
        #pragma unroll
        for (int u = 0; u < 4; u++) {
            int idx = u * 256 + tid;
            int r   = idx >> 3;
            int c   = idx & 7;
            size_t gb   = (size_t)(n0 + r) * K + koff + c * 4;
            uint32_t so = (uint32_t)(r * 128 + ((c ^ (r & 7)) * 16));
            cp16(sbase + BF_B + so, Bf + gb);
        }
    };

    // prologue: 2 stages in flight
    issue(usm, kb);                   CP_COMMIT();
    issue(usm + STG_BYTES, kb + GBK); CP_COMMIT();

    // warp mapping: 2m x 4n, warp tile 64x32
    const int w    = tid >> 5;
    const int lane = tid & 31;
    const int wm   = (w & 1) * 64;
    const int wn   = (w >> 1) * 32;
    const int g    = lane >> 3;
    const int rr   = lane & 7;
    const int bn   = lane >> 2;       // n-row within 8-tile for B conversion
    const int bk   = (lane & 3) * 2;  // k pair base within 16

    float acc[4][4][4];
    #pragma unroll
    for (int i = 0; i < 4; i++)
        #pragma unroll
        for (int j = 0; j < 4; j++)
            #pragma unroll
            for (int c = 0; c < 4; c++) acc[i][j][c] = 0.0f;

    int s = 0;
    for (int it = 0; it < iters; ++it) {
        CP_WAIT(1);              // stage s (for iter it) resident
        __syncthreads();         // also: all warps done reading stage (it-1)%3

        // refill the stage consumed at it-1 with data for it+2
        if (it + 2 < iters) {
            int s2 = s + 2; if (s2 >= NSTAGE) s2 -= NSTAGE;
            issue(usm + (uint32_t)s2 * STG_BYTES, kb + (it + 2) * GBK);
        }
        CP_COMMIT();             // uniform group counting

        const uint32_t uS  = usm + (uint32_t)s * STG_BYTES;
        const uint32_t uAh = uS + AH_B;
        const uint32_t uAl = uS + AL_B;
        const float*   sB  = smf + ((uint32_t)s * STG_BYTES + BF_B) / 4;

        #pragma unroll
        for (int ks = 0; ks < 2; ks++) {
            const int cA = ks * 2 + (g >> 1);       // A chunk (8 bf16 = 16B)
            const int f0 = ks * 16 + bk;            // B float index (p0)

            // ---- B fragments from fp32 smem (hi/lo built in registers) ----
            uint32_t bh[4][2], bl[4][2];
            #pragma unroll
            for (int ni = 0; ni < 4; ni++) {
                int rB = wn + ni * 8 + bn;
                int c0 = f0 >> 2;
                int c1 = c0 + 2;
                const float* p0p = sB + rB * 32 + ((c0 ^ (rB & 7)) << 2) + (f0 & 3);
                const float* p1p = sB + rB * 32 + ((c1 ^ (rB & 7)) << 2) + (f0 & 3);
                float2 p0 = *(const float2*)p0p;
                float2 p1 = *(const float2*)p1p;
                cvt_pair(p0, bh[ni][0], bl[ni][0]);
                cvt_pair(p1, bh[ni][1], bl[ni][1]);
            }
            // ---- A fragments (ldmatrix, swizzled) + MMAs ----
            #pragma unroll
            for (int mi = 0; mi < 4; mi++) {
                int arow = wm + mi * 16 + (g & 1) * 8 + rr;
                uint32_t off = (uint32_t)(arow * 64 + ((cA ^ ((arow >> 1) & 3)) * 16));
                uint32_t ah[4], al[4];
                ldmx4(ah, uAh + off);
                ldmx4(al, uAl + off);
                #pragma unroll
                for (int ni = 0; ni < 4; ni++) {
                    mma16816(acc[mi][ni], ah, bh[ni][0], bh[ni][1]);
                    mma16816(acc[mi][ni], al, bh[ni][0], bh[ni][1]);
                    mma16816(acc[mi][ni], ah, bl[ni][0], bl[ni][1]);
                }
            }
        }
        s = (s == NSTAGE - 1) ? 0 : s + 1;
    }

    // ---- epilogue ----
    const int erow = lane >> 2;
    const int ecol = (lane & 3) * 2;
    #pragma unroll
    for (int mi = 0; mi < 4; mi++) {
        #pragma unroll
        for (int ni = 0; ni < 4; ni++) {
            int r0 = m0 + wm + mi * 16 + erow;
            int c0 = n0 + wn + ni * 8 + ecol;
            float* p0 = C + (size_t)r0 * ldc + c0;
            float* p1 = C + (size_t)(r0 + 8) * ldc + c0;
            if (EPI == 0) {
                *(float2*)p0 = make_float2(acc[mi][ni][0], acc[mi][ni][1]);
                *(float2*)p1 = make_float2(acc[mi][ni][2], acc[mi][ni][3]);
            } else {
                atomicAdd(p0,     acc[mi][ni][0]);
                atomicAdd(p0 + 1, acc[mi][ni][1]);
                atomicAdd(p1,     acc[mi][ni][2]);
                atomicAdd(p1 + 1, acc[mi][ni][3]);
            }
        }
    }
}

// ---------------- small helpers ----------------
__global__ void zero_kernel(float* __restrict__ p, int n) {
    int i = blockIdx.x * blockDim.x + threadIdx.x;
    if (i < n) p[i] = 0.0f;
}

__global__ void precompute_A_kernel(const float* __restrict__ A_log) {
    int i = blockIdx.x * blockDim.x + threadIdx.x;
    if (i < DINNER * DSTATE) g_A[i] = -expf(A_log[i]);
}

// split fp32 -> bf16 hi + bf16 lo (residual), float4-vectorized (A operands only)
__global__ void split_bf16_kernel(const float4* __restrict__ in,
                                  __nv_bfloat162* __restrict__ hi,
                                  __nv_bfloat162* __restrict__ lo, int n4) {
    int i = blockIdx.x * blockDim.x + threadIdx.x;
    if (i >= n4) return;
    float4 v = in[i];
    __nv_bfloat162 h01 = __floats2bfloat162_rn(v.x, v.y);
    __nv_bfloat162 h23 = __floats2bfloat162_rn(v.z, v.w);
    float lx = v.x - __bfloat162float(h01.x);
    float ly = v.y - __bfloat162float(h01.y);
    float lz = v.z - __bfloat162float(h23.x);
    float lw = v.w - __bfloat162float(h23.y);
    hi[2*i]   = h01;
    hi[2*i+1] = h23;
    lo[2*i]   = __floats2bfloat162_rn(lx, ly);
    lo[2*i+1] = __floats2bfloat162_rn(lz, lw);
}

// ---------------- fp32 tiled SGEMM (small GEMMs) ----------------
template<int BM, int BN, int BK, int TM, int TN, int EPI>
__global__ void __launch_bounds__((BM/TM)*(BN/TN))
sgemm_nt(const float* __restrict__ A, int lda,
         const float* __restrict__ Bm, int ldb,
         float* __restrict__ C, int ldc,
         int M, int N, int K, int kChunk,
         const float* __restrict__ bias)
{
    constexpr int THREADS = (BM/TM)*(BN/TN);
    constexpr int KQ = BK / 4;
    constexpr int A4 = BM * BK / 4;
    constexpr int B4 = BN * BK / 4;

    __shared__ float As[BK][BM];
    __shared__ float Bs[BK][BN];

    const int tid = threadIdx.x;
    const int n0  = blockIdx.x * BN;
    const int m0  = blockIdx.y * BM;
    const int kb  = blockIdx.z * kChunk;
    const int ke  = (kb + kChunk < K) ? (kb + kChunk) : K;

    const int tc = tid % (BN / TN);
    const int tr = tid / (BN / TN);

    float acc[TM][TN];
    #pragma unroll
    for (int i = 0; i < TM; i++)
        #pragma unroll
        for (int j = 0; j < TN; j++) acc[i][j] = 0.0f;

    for (int k0 = kb; k0 < ke; k0 += BK) {
        #pragma unroll
        for (int i = tid; i < A4; i += THREADS) {
            int m  = i / KQ;
            int kq = i % KQ;
            float4 v = *(const float4*)&A[(size_t)(m0 + m) * lda + k0 + kq * 4];
            As[kq*4+0][m] = v.x; As[kq*4+1][m] = v.y;
            As[kq*4+2][m] = v.z; As[kq*4+3][m] = v.w;
        }
        #pragma unroll
        for (int i = tid; i < B4; i += THREADS) {
            int n  = i / KQ;
            int kq = i % KQ;
            float4 v = *(const float4*)&Bm[(size_t)(n0 + n) * ldb + k0 + kq * 4];
            Bs[kq*4+0][n] = v.x; Bs[kq*4+1][n] = v.y;
            Bs[kq*4+2][n] = v.z; Bs[kq*4+3][n] = v.w;
        }
        __syncthreads();

        #pragma unroll
        for (int kk = 0; kk < BK; kk++) {
            float a[TM], b[TN];
            #pragma unroll
            for (int i = 0; i < TM; i++) a[i] = As[kk][tr*TM + i];
            #pragma unroll
            for (int j = 0; j < TN; j++) b[j] = Bs[kk][tc*TN + j];
            #pragma unroll
            for (int i = 0; i < TM; i++)
                #pragma unroll
                for (int j = 0; j < TN; j++)
                    acc[i][j] = fmaf(a[i], b[j], acc[i][j]);
        }
        __syncthreads();
    }

    #pragma unroll
    for (int i = 0; i < TM; i++) {
        int m = m0 + tr*TM + i;
        #pragma unroll
        for (int j = 0; j < TN; j++) {
            int n = n0 + tc*TN + j;
            float v = acc[i][j];
            if (EPI == 0) {
                C[(size_t)m * ldc + n] = v;
            } else if (EPI == 1) {
                atomicAdd(&C[(size_t)m * ldc + n], v);
            } else {
                float x = v + bias[n];
                float r2 = fmaxf(x, 0.0f) + log1pf(__expf(-fabsf(x)));
                C[(size_t)m * ldc + n] = r2;
            }
        }
    }
}

// ---------------- conv window shift + SiLU ----------------
__global__ void conv_kernel(const float* __restrict__ cs_in,
                            const float* __restrict__ conv_w,
                            const float* __restrict__ conv_b,
                            float* __restrict__ cs_out)
{
    int idx = blockIdx.x * blockDim.x + threadIdx.x;
    int b = idx >> 13;
    int d = idx & (DINNER - 1);
    float4 cs = ((const float4*)cs_in)[idx];
    float4 w  = ((const float4*)conv_w)[d];
    float xi  = g_xz[(size_t)b * (2*DINNER) + d];
    float s = cs.y*w.x + cs.z*w.y + cs.w*w.z + xi*w.w + conv_b[d];
    float sig = 1.0f / (1.0f + __expf(-s));
    g_xc[idx] = s * sig;
    ((float4*)cs_out)[idx] = make_float4(cs.y, cs.z, cs.w, xi);
}

// ---------------- SSM state update + y (emits y as bf16 hi/lo) --------------
__global__ void ssm_kernel(const float* __restrict__ ssm_in,
                           const float* __restrict__ D_param,
                           float* __restrict__ ssm_out)
{
    __shared__ float bm[DSTATE], cm[DSTATE];
    const int b = blockIdx.y;
    const int d = blockIdx.x * blockDim.x + threadIdx.x;
    if (threadIdx.x < 2*DSTATE) {
        float v = g_xdb[b * XPN + DTRANK + threadIdx.x];
        if (threadIdx.x < DSTATE) bm[threadIdx.x] = v;
        else                      cm[threadIdx.x - DSTATE] = v;
    }
    __syncthreads();

    const int bd = b * DINNER + d;
    const float dtv = g_dt[bd];
    const float xcv = g_xc[bd];
    const float xdt = xcv * dtv;
    const size_t base = (size_t)bd * DSTATE;

    float yacc = 0.0f;
    #pragma unroll
    for (int n = 0; n < DSTATE; n += 4) {
        float4 a  = *(const float4*)&g_A[d * DSTATE + n];
        float4 st = *(const float4*)&ssm_in[base + n];
        float4 ns;
        ns.x = st.x * __expf(a.x * dtv) + xdt * bm[n+0];
        ns.y = st.y * __expf(a.y * dtv) + xdt * bm[n+1];
        ns.z = st.z * __expf(a.z * dtv) + xdt * bm[n+2];
        ns.w = st.w * __expf(a.w * dtv) + xdt * bm[n+3];
        yacc += ns.x * cm[n+0] + ns.y * cm[n+1] + ns.z * cm[n+2] + ns.w * cm[n+3];
        *(float4*)&ssm_out[base + n] = ns;
    }
    yacc += D_param[d] * xcv;
    float zv = g_xz[(size_t)b * (2*DINNER) + DINNER + d];
    yacc *= zv / (1.0f + __expf(-zv));

    __nv_bfloat16 h = __float2bfloat16(yacc);
    g_yhi[bd] = h;
    g_ylo[bd] = __float2bfloat16(yacc - __bfloat162float(h));
}

// ---------------- launch ----------------
extern "C" void kernel_launch(void* const* d_in, const int* in_sizes, int n_in,
                              void* d_out, int out_size)
{
    const float* x       = (const float*)d_in[0];
    const float* cs_in   = (const float*)d_in[1];
    const float* ssm_in  = (const float*)d_in[2];
    const float* W_in    = (const float*)d_in[3];
    const float* conv_w  = (const float*)d_in[4];
    const float* conv_b  = (const float*)d_in[5];
    const float* W_xproj = (const float*)d_in[6];
    const float* W_dt    = (const float*)d_in[7];
    const float* b_dt    = (const float*)d_in[8];
    const float* A_log   = (const float*)d_in[9];
    const float* D_param = (const float*)d_in[10];
    const float* W_out   = (const float*)d_in[11];

    float* out     = (float*)d_out;
    float* cs_out  = out + (size_t)BB * DMODEL;
    float* ssm_out = cs_out + (size_t)BB * DINNER * 4;

    void *p_xz, *p_xc, *p_xdb, *p_dt, *p_xhi, *p_xlo, *p_yhi, *p_ylo;
    cudaGetSymbolAddress(&p_xz,  g_xz);
    cudaGetSymbolAddress(&p_xc,  g_xc);
    cudaGetSymbolAddress(&p_xdb, g_xdb);
    cudaGetSymbolAddress(&p_dt,  g_dt);
    cudaGetSymbolAddress(&p_xhi, g_xhi);
    cudaGetSymbolAddress(&p_xlo, g_xlo);
    cudaGetSymbolAddress(&p_yhi, g_yhi);
    cudaGetSymbolAddress(&p_ylo, g_ylo);

    const int HSM = NSTAGE * STG_BYTES;   // 98304 bytes -> 2 CTAs/SM
    cudaFuncSetAttribute(hmma_gemm<0,1>, cudaFuncAttributeMaxDynamicSharedMemorySize, HSM);
    cudaFuncSetAttribute(hmma_gemm<1,8>, cudaFuncAttributeMaxDynamicSharedMemorySize, HSM);

    // launches 0-2, then GEMM1 as the 4th launch (ncu window profiles index 3)
    zero_kernel<<<(BB*XPN + 255)/256, 256>>>((float*)p_xdb, BB*XPN);
    zero_kernel<<<(BB*DMODEL + 255)/256, 256>>>(out, BB*DMODEL);
    split_bf16_kernel<<<(BB*DMODEL/4 + 255)/256, 256>>>(
        (const float4*)x, (__nv_bfloat162*)p_xhi, (__nv_bfloat162*)p_xlo, BB*DMODEL/4);

    // GEMM1: xz[256,16384] = x @ W_in^T   (B = W_in fp32 direct)
    hmma_gemm<0,1><<<dim3((2*DINNER)/GBN, BB/GBM, 1), 256, HSM>>>(
        (const __nv_bfloat16*)p_xhi, (const __nv_bfloat16*)p_xlo,
        W_in, (float*)p_xz, 2*DINNER, DMODEL);

    precompute_A_kernel<<<(DINNER*DSTATE + 255)/256, 256>>>(A_log);

    // conv + SiLU
    conv_kernel<<<(BB*DINNER)/256, 256>>>(cs_in, conv_w, conv_b, cs_out);

    // GEMM3: x_db[256,160] = xc @ W_xproj^T  (fp32, BK=32, split-K=16, atomic)
    sgemm_nt<64,32,32,4,4,1><<<dim3(XPN/32, BB/64, 16), 128>>>(
        (const float*)p_xc, DINNER, W_xproj, DINNER, (float*)p_xdb, XPN,
        BB, XPN, DINNER, DINNER/16, nullptr);

    // GEMM4: dt[256,8192] = softplus(x_db[:, :128] @ W_dt^T + b_dt)  (fp32, BK=32)
    sgemm_nt<64,64,32,4,4,2><<<dim3(DINNER/64, BB/64, 1), 256>>>(
        (const float*)p_xdb, XPN, W_dt, DTRANK, (float*)p_dt, DINNER,
        BB, DINNER, DTRANK, DTRANK, b_dt);

    // SSM update + y (emits yhi/ylo)
    ssm_kernel<<<dim3(DINNER/256, BB), 256>>>(ssm_in, D_param, ssm_out);

    // GEMM6: out[256,2048] = y @ W_out^T  (split-K=8 -> 256 CTAs = 2/SM, atomic)
    hmma_gemm<1,8><<<dim3(DMODEL/GBN, BB/GBM, 8), 256, HSM>>>(
        (const __nv_bfloat16*)p_yhi, (const __nv_bfloat16*)p_ylo,
        W_out, out, DMODEL, DINNER);
}